// round 6
// baseline (speedup 1.0000x reference)
#include <cuda_runtime.h>
#include <cuda_bf16.h>
#include <math.h>
#include <cstdint>

// Problem constants
#define S        2048
#define DMODEL   2048
#define NHEADS   32
#define NKVHEADS 8
#define HDIM     64
#define KVDIM    (NKVHEADS * HDIM)   // 512
#define QKV_N    3072                // fused Q(2048) + K(512) + V(512)

// ---------------------------------------------------------------------------
// Device-global scratch (allocation-free, graph-capturable)
// ---------------------------------------------------------------------------
__device__ __nv_bfloat16 g_xh[S * DMODEL],      g_xl[S * DMODEL];
__device__ __nv_bfloat16 g_wh[QKV_N * DMODEL],  g_wl[QKV_N * DMODEL];   // stacked Wq|Wk|Wv
__device__ __nv_bfloat16 g_woh[DMODEL * DMODEL], g_wol[DMODEL * DMODEL];
__device__ __nv_bfloat16 g_qkvh[S * QKV_N],     g_qkvl[S * QKV_N];
__device__ __nv_bfloat16 g_ch[S * DMODEL],      g_cl[S * DMODEL];

__device__ __forceinline__ uint32_t smem_u32(const void* p) {
    uint32_t a;
    asm("{ .reg .u64 t; cvta.to.shared.u64 t, %1; cvt.u32.u64 %0, t; }"
        : "=r"(a) : "l"(p));
    return a;
}

__device__ __forceinline__ uint32_t pack_bf2(float x, float y) {
    __nv_bfloat162 h = __floats2bfloat162_rn(x, y);
    return *(uint32_t*)&h;
}

#define MMA_BF16(d, a0, a1, a2, a3, b0, b1) \
    asm volatile( \
        "mma.sync.aligned.m16n8k16.row.col.f32.bf16.bf16.f32 " \
        "{%0,%1,%2,%3}, {%4,%5,%6,%7}, {%8,%9}, {%0,%1,%2,%3};" \
        : "+f"((d)[0]), "+f"((d)[1]), "+f"((d)[2]), "+f"((d)[3]) \
        : "r"(a0), "r"(a1), "r"(a2), "r"(a3), "r"(b0), "r"(b1))

#define CP_ASYNC16(dst, src) \
    asm volatile("cp.async.cg.shared.global [%0], [%1], 16;" :: "r"(dst), "l"(src))

#define LDSM_X4(r0, r1, r2, r3, addr) \
    asm volatile("ldmatrix.sync.aligned.m8n8.x4.shared.b16 {%0,%1,%2,%3}, [%4];" \
                 : "=r"(r0), "=r"(r1), "=r"(r2), "=r"(r3) : "r"(addr))

// ---------------------------------------------------------------------------
// fp32 -> (hi, lo) bf16 split kernel
// ---------------------------------------------------------------------------
__global__ __launch_bounds__(256) void split_kernel(
    const float* __restrict__ in, __nv_bfloat16* __restrict__ hi,
    __nv_bfloat16* __restrict__ lo, int n4)
{
    int i = blockIdx.x * blockDim.x + threadIdx.x;
    int stride = gridDim.x * blockDim.x;
    const float4* in4 = (const float4*)in;
    __nv_bfloat162* h2 = (__nv_bfloat162*)hi;
    __nv_bfloat162* l2 = (__nv_bfloat162*)lo;
    for (; i < n4; i += stride) {
        float4 v = in4[i];
        __nv_bfloat16 hx = __float2bfloat16_rn(v.x);
        __nv_bfloat16 hy = __float2bfloat16_rn(v.y);
        __nv_bfloat16 hz = __float2bfloat16_rn(v.z);
        __nv_bfloat16 hw = __float2bfloat16_rn(v.w);
        __nv_bfloat16 lx = __float2bfloat16_rn(v.x - __bfloat162float(hx));
        __nv_bfloat16 ly = __float2bfloat16_rn(v.y - __bfloat162float(hy));
        __nv_bfloat16 lz = __float2bfloat16_rn(v.z - __bfloat162float(hz));
        __nv_bfloat16 lw = __float2bfloat16_rn(v.w - __bfloat162float(hw));
        h2[2 * i + 0] = __nv_bfloat162(hx, hy);
        h2[2 * i + 1] = __nv_bfloat162(hz, hw);
        l2[2 * i + 0] = __nv_bfloat162(lx, ly);
        l2[2 * i + 1] = __nv_bfloat162(lz, lw);
    }
}

// ---------------------------------------------------------------------------
// bf16 mma.sync GEMM, 3-term split (Ah*Bh + Al*Bh + Ah*Bl), fp32 accum.
// CTA tile 128x256, BK=64, 256 threads (2M x 4N warps), warp tile 64x64.
// 3-stage cp.async pipeline, ldmatrix.x4 fragment loads.
// ---------------------------------------------------------------------------
#define BM 128
#define BN 256
#define GSTR 144                         // smem row stride bytes (128 + 16 pad)
#define TILE_A (128 * GSTR)              // 18432
#define TILE_BB (256 * GSTR)             // 36864
#define STAGE_B (TILE_A + TILE_BB)       // 55296
#define GEMM_SMEM (3 * STAGE_B)          // 165888

__global__ __launch_bounds__(256, 1) void gemm_mma_kernel(
    const __nv_bfloat16* __restrict__ Ah, const __nv_bfloat16* __restrict__ Al,
    const __nv_bfloat16* __restrict__ Bh, const __nv_bfloat16* __restrict__ Bl,
    float* __restrict__ Cf, __nv_bfloat16* __restrict__ Chi,
    __nv_bfloat16* __restrict__ Clo,
    int Ktot, int Ncols, const float* __restrict__ bias,
    int qcols, float qscale)
{
    extern __shared__ __align__(16) char smem[];
    const uint32_t sbase = smem_u32(smem);

    const int tid   = threadIdx.x;
    const int lane  = tid & 31;
    const int wid   = tid >> 5;
    const int warpM = wid >> 2;      // 0..1 (m offset 64*warpM)
    const int warpN = wid & 3;       // 0..3 (n offset 64*warpN)
    const int g     = lane >> 2;     // 0..7
    const int t     = lane & 3;      // 0..3
    const int mb = blockIdx.y, nb = blockIdx.x;

    const int KT = Ktot / 64;
    const int NT = 3 * KT;
    const size_t rowKb = (size_t)Ktot * 2;

    float acc[4][8][4];
#pragma unroll
    for (int mt = 0; mt < 4; ++mt)
#pragma unroll
        for (int nt = 0; nt < 8; ++nt)
#pragma unroll
            for (int c = 0; c < 4; ++c) acc[mt][nt][c] = 0.f;

    auto load_stage = [&](int kt, int stg) {
        const int seg = kt / KT;
        const int kk  = (kt - seg * KT) * 64;
        const char* aSrc = (const char*)((seg == 1) ? Al : Ah)
                         + (size_t)(mb * BM) * rowKb + (size_t)kk * 2;
        const char* bSrc = (const char*)((seg == 2) ? Bl : Bh)
                         + (size_t)(nb * BN) * rowKb + (size_t)kk * 2;
        const uint32_t sa = sbase + stg * STAGE_B;
        const uint32_t sb = sa + TILE_A;
#pragma unroll
        for (int c = tid; c < 3072; c += 256) {
            const int ch = c & 7;
            if (c < 1024) {
                const int row = c >> 3;
                CP_ASYNC16(sa + row * GSTR + ch * 16,
                           aSrc + (size_t)row * rowKb + ch * 16);
            } else {
                const int row = (c - 1024) >> 3;
                CP_ASYNC16(sb + row * GSTR + ch * 16,
                           bSrc + (size_t)row * rowKb + ch * 16);
            }
        }
        asm volatile("cp.async.commit_group;");
    };

    // ldmatrix per-lane address components (byte offsets within a tile)
    const uint32_t aRowOff = (uint32_t)((warpM * 64 + (lane & 15)) * GSTR
                                        + ((lane >> 4) << 4));
    const uint32_t bRowOff = (uint32_t)((warpN * 64 + ((lane >> 4) & 1) * 8 + (lane & 7)) * GSTR
                                        + (((lane >> 3) & 1) << 4));

    auto compute = [&](int stg) {
        const uint32_t aT = sbase + stg * STAGE_B;
        const uint32_t bT = aT + TILE_A;
#pragma unroll
        for (int ks = 0; ks < 4; ++ks) {
            uint32_t a[4][4];
#pragma unroll
            for (int mt = 0; mt < 4; ++mt)
                LDSM_X4(a[mt][0], a[mt][1], a[mt][2], a[mt][3],
                        aT + aRowOff + mt * (16 * GSTR) + ks * 32);
            uint32_t b[8][2];
#pragma unroll
            for (int j = 0; j < 4; ++j) {
                uint32_t r0, r1, r2, r3;
                LDSM_X4(r0, r1, r2, r3, bT + bRowOff + j * (16 * GSTR) + ks * 32);
                b[2 * j][0] = r0; b[2 * j][1] = r1;
                b[2 * j + 1][0] = r2; b[2 * j + 1][1] = r3;
            }
#pragma unroll
            for (int nt = 0; nt < 8; ++nt)
#pragma unroll
                for (int mt = 0; mt < 4; ++mt)
                    MMA_BF16(acc[mt][nt], a[mt][0], a[mt][1], a[mt][2], a[mt][3],
                             b[nt][0], b[nt][1]);
        }
    };

    load_stage(0, 0);
    load_stage(1, 1);

    int stg = 0;
    for (int kt = 0; kt < NT; ++kt) {
        if (kt + 1 < NT) { asm volatile("cp.async.wait_group 1;"); }
        else             { asm volatile("cp.async.wait_group 0;"); }
        __syncthreads();
        if (kt + 2 < NT) {
            int s2 = stg + 2; if (s2 >= 3) s2 -= 3;
            load_stage(kt + 2, s2);
        }
        compute(stg);
        if (++stg == 3) stg = 0;
    }

    // Epilogue
    const int colBase = nb * BN;
    const float sc = (colBase < qcols) ? qscale : 1.0f;
    const int row0 = mb * BM + warpM * 64 + g;
    const int col0 = colBase + warpN * 64 + t * 2;
#pragma unroll
    for (int mt = 0; mt < 4; ++mt) {
#pragma unroll
        for (int nt = 0; nt < 8; ++nt) {
            const int col = col0 + nt * 8;
            const int rA = row0 + mt * 16;
            const int rB = rA + 8;
            float f0 = acc[mt][nt][0] * sc, f1 = acc[mt][nt][1] * sc;
            float f2 = acc[mt][nt][2] * sc, f3 = acc[mt][nt][3] * sc;
            if (Cf) {
                float bx = 0.f, by = 0.f;
                if (bias) { bx = bias[col]; by = bias[col + 1]; }
                *(float2*)(Cf + (size_t)rA * Ncols + col) = make_float2(f0 + bx, f1 + by);
                *(float2*)(Cf + (size_t)rB * Ncols + col) = make_float2(f2 + bx, f3 + by);
            } else {
                __nv_bfloat162 hA = __floats2bfloat162_rn(f0, f1);
                __nv_bfloat162 hB = __floats2bfloat162_rn(f2, f3);
                __nv_bfloat162 lA = __floats2bfloat162_rn(
                    f0 - __bfloat162float(hA.x), f1 - __bfloat162float(hA.y));
                __nv_bfloat162 lB = __floats2bfloat162_rn(
                    f2 - __bfloat162float(hB.x), f3 - __bfloat162float(hB.y));
                *(__nv_bfloat162*)(Chi + (size_t)rA * Ncols + col) = hA;
                *(__nv_bfloat162*)(Chi + (size_t)rB * Ncols + col) = hB;
                *(__nv_bfloat162*)(Clo + (size_t)rA * Ncols + col) = lA;
                *(__nv_bfloat162*)(Clo + (size_t)rB * Ncols + col) = lB;
            }
        }
    }
}

// ---------------------------------------------------------------------------
// Tensor-core causal flash attention (fused QKV input, stride 3072).
// BQ=128 per CTA, BKV=64 per iter, 4 warps. ldmatrix for all fragments.
// ---------------------------------------------------------------------------
#define ATS 72
#define AT_QBYTES (128 * ATS * 2)
#define AT_TBYTES (64 * ATS * 2)
#define ATTN_SMEM (2 * AT_QBYTES + 8 * AT_TBYTES)   // 110592

__global__ __launch_bounds__(128) void attn_tc_kernel(
    const __nv_bfloat16* __restrict__ QKVh, const __nv_bfloat16* __restrict__ QKVl,
    __nv_bfloat16* __restrict__ Ch, __nv_bfloat16* __restrict__ Cl)
{
    extern __shared__ __align__(16) char smem[];
    const int qb  = (int)gridDim.x - 1 - (int)blockIdx.x;
    const int h   = blockIdx.y;
    const int kvh = h >> 2;
    const int tid = threadIdx.x, wid = tid >> 5, lane = tid & 31;
    const int g = lane >> 2, t = lane & 3;

    const uint32_t uQh = smem_u32(smem);
    const uint32_t uQl = uQh + AT_QBYTES;
    const uint32_t uKV = uQl + AT_QBYTES;

    const size_t rowB = QKV_N * 2;

    // Q loads (once)
    {
        const char* srcH = (const char*)(QKVh + (size_t)(qb * 128) * QKV_N + h * HDIM);
        const char* srcL = (const char*)(QKVl + (size_t)(qb * 128) * QKV_N + h * HDIM);
#pragma unroll
        for (int c = tid; c < 1024; c += 128) {
            const int row = c >> 3, ch = c & 7;
            const uint32_t so = row * 144 + ch * 16;
            const size_t go = (size_t)row * rowB + ch * 16;
            CP_ASYNC16(uQh + so, srcH + go);
            CP_ASYNC16(uQl + so, srcL + go);
        }
    }

    const size_t koff = (size_t)DMODEL + kvh * HDIM;
    const size_t voff = (size_t)DMODEL + KVDIM + kvh * HDIM;

    auto load_kv = [&](int jb, int buf) {
        const size_t gbase = (size_t)(jb * 64) * QKV_N;
        const __nv_bfloat16* srcs[4] = {QKVh + gbase + koff, QKVl + gbase + koff,
                                        QKVh + gbase + voff, QKVl + gbase + voff};
#pragma unroll
        for (int w4 = 0; w4 < 4; ++w4) {
            const char* src = (const char*)srcs[w4];
            const uint32_t dst = uKV + (buf * 4 + w4) * AT_TBYTES;
#pragma unroll
            for (int c = tid; c < 512; c += 128) {
                const int row = c >> 3, ch = c & 7;
                CP_ASYNC16(dst + row * 144 + ch * 16,
                           src + (size_t)row * rowB + ch * 16);
            }
        }
    };

    load_kv(0, 0);
    asm volatile("cp.async.commit_group;");

    float o[2][8][4];
#pragma unroll
    for (int mt = 0; mt < 2; ++mt)
#pragma unroll
        for (int nt = 0; nt < 8; ++nt)
#pragma unroll
            for (int c = 0; c < 4; ++c) o[mt][nt][c] = 0.f;
    float mst[2][2] = {{-1e30f, -1e30f}, {-1e30f, -1e30f}};
    float lst[2][2] = {{0.f, 0.f}, {0.f, 0.f}};

    const int jbmax = 2 * qb + 1;

    // ldmatrix address components
    const uint32_t qRowOff = (uint32_t)((wid * 32 + (lane & 15)) * 144
                                        + ((lane >> 4) << 4));
    const uint32_t kRowOff = (uint32_t)((((lane >> 4) & 1) * 8 + (lane & 7)) * 144
                                        + (((lane >> 3) & 1) << 4));

    for (int jb = 0; jb <= jbmax; ++jb) {
        const int buf = jb & 1;
        asm volatile("cp.async.wait_group 0;");
        __syncthreads();
        if (jb + 1 <= jbmax) {
            load_kv(jb + 1, buf ^ 1);
            asm volatile("cp.async.commit_group;");
        }

        float s[2][8][4];
#pragma unroll
        for (int mt = 0; mt < 2; ++mt)
#pragma unroll
            for (int nt = 0; nt < 8; ++nt)
#pragma unroll
                for (int c = 0; c < 4; ++c) s[mt][nt][c] = 0.f;

        const uint32_t uKhT = uKV + (buf * 4 + 0) * AT_TBYTES;
        const uint32_t uKlT = uKV + (buf * 4 + 1) * AT_TBYTES;
        const uint32_t uVhT = uKV + (buf * 4 + 2) * AT_TBYTES;
        const uint32_t uVlT = uKV + (buf * 4 + 3) * AT_TBYTES;

#pragma unroll
        for (int ks = 0; ks < 4; ++ks) {
            uint32_t aH[2][4], aL[2][4];
#pragma unroll
            for (int mt = 0; mt < 2; ++mt) {
                LDSM_X4(aH[mt][0], aH[mt][1], aH[mt][2], aH[mt][3],
                        uQh + qRowOff + mt * (16 * 144) + ks * 32);
                LDSM_X4(aL[mt][0], aL[mt][1], aL[mt][2], aL[mt][3],
                        uQl + qRowOff + mt * (16 * 144) + ks * 32);
            }
            uint32_t bh[8][2], bl[8][2];
#pragma unroll
            for (int j = 0; j < 4; ++j) {
                uint32_t r0, r1, r2, r3;
                LDSM_X4(r0, r1, r2, r3, uKhT + kRowOff + j * (16 * 144) + ks * 32);
                bh[2 * j][0] = r0; bh[2 * j][1] = r1;
                bh[2 * j + 1][0] = r2; bh[2 * j + 1][1] = r3;
                LDSM_X4(r0, r1, r2, r3, uKlT + kRowOff + j * (16 * 144) + ks * 32);
                bl[2 * j][0] = r0; bl[2 * j][1] = r1;
                bl[2 * j + 1][0] = r2; bl[2 * j + 1][1] = r3;
            }
#pragma unroll
            for (int nt = 0; nt < 8; ++nt)
#pragma unroll
                for (int mt = 0; mt < 2; ++mt) {
                    MMA_BF16(s[mt][nt], aH[mt][0], aH[mt][1], aH[mt][2], aH[mt][3],
                             bh[nt][0], bh[nt][1]);
                    MMA_BF16(s[mt][nt], aL[mt][0], aL[mt][1], aL[mt][2], aL[mt][3],
                             bh[nt][0], bh[nt][1]);
                    MMA_BF16(s[mt][nt], aH[mt][0], aH[mt][1], aH[mt][2], aH[mt][3],
                             bl[nt][0], bl[nt][1]);
                }
        }

        if (jb >= 2 * qb) {
            const int q0 = qb * 128 + wid * 32;
            const int kvb = jb * 64;
#pragma unroll
            for (int mt = 0; mt < 2; ++mt)
#pragma unroll
                for (int nt = 0; nt < 8; ++nt) {
                    const int kv0 = kvb + nt * 8 + 2 * t;
                    const int r0 = q0 + mt * 16 + g;
                    if (kv0 > r0)         s[mt][nt][0] = -1e30f;
                    if (kv0 + 1 > r0)     s[mt][nt][1] = -1e30f;
                    if (kv0 > r0 + 8)     s[mt][nt][2] = -1e30f;
                    if (kv0 + 1 > r0 + 8) s[mt][nt][3] = -1e30f;
                }
        }

#pragma unroll
        for (int mt = 0; mt < 2; ++mt)
#pragma unroll
            for (int hh = 0; hh < 2; ++hh) {
                float vmax = -1e30f;
#pragma unroll
                for (int nt = 0; nt < 8; ++nt)
                    vmax = fmaxf(vmax, fmaxf(s[mt][nt][2 * hh], s[mt][nt][2 * hh + 1]));
                vmax = fmaxf(vmax, __shfl_xor_sync(0xffffffffu, vmax, 1));
                vmax = fmaxf(vmax, __shfl_xor_sync(0xffffffffu, vmax, 2));
                const float mo = mst[mt][hh];
                const float mn = fmaxf(mo, vmax);
                const float corr = __expf(mo - mn);
                float ls = 0.f;
#pragma unroll
                for (int nt = 0; nt < 8; ++nt) {
                    float p0 = __expf(s[mt][nt][2 * hh] - mn);
                    float p1 = __expf(s[mt][nt][2 * hh + 1] - mn);
                    s[mt][nt][2 * hh] = p0;
                    s[mt][nt][2 * hh + 1] = p1;
                    ls += p0 + p1;
                }
                ls += __shfl_xor_sync(0xffffffffu, ls, 1);
                ls += __shfl_xor_sync(0xffffffffu, ls, 2);
                lst[mt][hh] = lst[mt][hh] * corr + ls;
                mst[mt][hh] = mn;
#pragma unroll
                for (int nt = 0; nt < 8; ++nt) {
                    o[mt][nt][2 * hh] *= corr;
                    o[mt][nt][2 * hh + 1] *= corr;
                }
            }

        uint32_t pH[2][8][2], pL[2][8][2];
#pragma unroll
        for (int mt = 0; mt < 2; ++mt)
#pragma unroll
            for (int nt = 0; nt < 8; ++nt) {
                float p0 = s[mt][nt][0], p1 = s[mt][nt][1];
                float p2 = s[mt][nt][2], p3 = s[mt][nt][3];
                __nv_bfloat162 h01 = __floats2bfloat162_rn(p0, p1);
                __nv_bfloat162 h23 = __floats2bfloat162_rn(p2, p3);
                pH[mt][nt][0] = *(uint32_t*)&h01;
                pH[mt][nt][1] = *(uint32_t*)&h23;
                pL[mt][nt][0] = pack_bf2(p0 - __bfloat162float(h01.x),
                                         p1 - __bfloat162float(h01.y));
                pL[mt][nt][1] = pack_bf2(p2 - __bfloat162float(h23.x),
                                         p3 - __bfloat162float(h23.y));
            }

        const uint32_t lmrow = lane & 15;
        const uint32_t lmcol = (lane >> 4) * 16;
#pragma unroll
        for (int kb = 0; kb < 4; ++kb) {
#pragma unroll
            for (int np = 0; np < 4; ++np) {
                const uint32_t lmoff = (kb * 16 + lmrow) * 144 + np * 32 + lmcol;
                uint32_t vh0, vh1, vh2, vh3, vl0, vl1, vl2, vl3;
                asm volatile("ldmatrix.sync.aligned.m8n8.x4.trans.shared.b16 "
                             "{%0,%1,%2,%3}, [%4];"
                             : "=r"(vh0), "=r"(vh1), "=r"(vh2), "=r"(vh3)
                             : "r"(uVhT + lmoff));
                asm volatile("ldmatrix.sync.aligned.m8n8.x4.trans.shared.b16 "
                             "{%0,%1,%2,%3}, [%4];"
                             : "=r"(vl0), "=r"(vl1), "=r"(vl2), "=r"(vl3)
                             : "r"(uVlT + lmoff));
#pragma unroll
                for (int mt = 0; mt < 2; ++mt) {
                    const uint32_t a0 = pH[mt][2 * kb][0], a1 = pH[mt][2 * kb][1];
                    const uint32_t a2 = pH[mt][2 * kb + 1][0], a3 = pH[mt][2 * kb + 1][1];
                    const uint32_t c0 = pL[mt][2 * kb][0], c1 = pL[mt][2 * kb][1];
                    const uint32_t c2 = pL[mt][2 * kb + 1][0], c3 = pL[mt][2 * kb + 1][1];
                    MMA_BF16(o[mt][2 * np], a0, a1, a2, a3, vh0, vh1);
                    MMA_BF16(o[mt][2 * np], c0, c1, c2, c3, vh0, vh1);
                    MMA_BF16(o[mt][2 * np], a0, a1, a2, a3, vl0, vl1);
                    MMA_BF16(o[mt][2 * np + 1], a0, a1, a2, a3, vh2, vh3);
                    MMA_BF16(o[mt][2 * np + 1], c0, c1, c2, c3, vh2, vh3);
                    MMA_BF16(o[mt][2 * np + 1], a0, a1, a2, a3, vl2, vl3);
                }
            }
        }
        __syncthreads();
    }

#pragma unroll
    for (int mt = 0; mt < 2; ++mt)
#pragma unroll
        for (int hh = 0; hh < 2; ++hh) {
            const float inv = 1.f / lst[mt][hh];
            const int row = qb * 128 + wid * 32 + mt * 16 + hh * 8 + g;
            const size_t gbase = (size_t)row * DMODEL + h * HDIM;
#pragma unroll
            for (int nt = 0; nt < 8; ++nt) {
                const int col = nt * 8 + 2 * t;
                float v0 = o[mt][nt][2 * hh] * inv;
                float v1 = o[mt][nt][2 * hh + 1] * inv;
                __nv_bfloat162 hv = __floats2bfloat162_rn(v0, v1);
                __nv_bfloat162 lv = __floats2bfloat162_rn(
                    v0 - __bfloat162float(hv.x), v1 - __bfloat162float(hv.y));
                *(__nv_bfloat162*)(Ch + gbase + col) = hv;
                *(__nv_bfloat162*)(Cl + gbase + col) = lv;
            }
        }
}

// ---------------------------------------------------------------------------
// Launcher
// ---------------------------------------------------------------------------
extern "C" void kernel_launch(void* const* d_in, const int* in_sizes, int n_in,
                              void* d_out, int out_size)
{
    const float* x   = (const float*)d_in[0];
    // d_in[1] = mask (int32 causal tril) — causality hardcoded
    const float* w_q = (const float*)d_in[2];
    const float* w_k = (const float*)d_in[3];
    const float* w_v = (const float*)d_in[4];
    const float* w_o = (const float*)d_in[5];
    const float* b_o = (const float*)d_in[6];
    float* out = (float*)d_out;

    __nv_bfloat16 *xh, *xl, *wh, *wl, *woh, *wol, *qkvh, *qkvl, *ch, *cl;
    cudaGetSymbolAddress((void**)&xh,   g_xh);   cudaGetSymbolAddress((void**)&xl,   g_xl);
    cudaGetSymbolAddress((void**)&wh,   g_wh);   cudaGetSymbolAddress((void**)&wl,   g_wl);
    cudaGetSymbolAddress((void**)&woh,  g_woh);  cudaGetSymbolAddress((void**)&wol,  g_wol);
    cudaGetSymbolAddress((void**)&qkvh, g_qkvh); cudaGetSymbolAddress((void**)&qkvl, g_qkvl);
    cudaGetSymbolAddress((void**)&ch,   g_ch);   cudaGetSymbolAddress((void**)&cl,   g_cl);

    cudaFuncSetAttribute(attn_tc_kernel, cudaFuncAttributeMaxDynamicSharedMemorySize,
                         ATTN_SMEM);
    cudaFuncSetAttribute(gemm_mma_kernel, cudaFuncAttributeMaxDynamicSharedMemorySize,
                         GEMM_SMEM);

    // Split inputs to bf16 hi/lo (weights stacked Wq|Wk|Wv)
    split_kernel<<<1024, 256>>>(x,   xh, xl, S * DMODEL / 4);
    split_kernel<<<1024, 256>>>(w_q, wh,                    wl,                    DMODEL * DMODEL / 4);
    split_kernel<<<1024, 256>>>(w_k, wh + DMODEL * DMODEL,  wl + DMODEL * DMODEL,  KVDIM * DMODEL / 4);
    split_kernel<<<1024, 256>>>(w_v, wh + (DMODEL + KVDIM) * DMODEL,
                                      wl + (DMODEL + KVDIM) * DMODEL, KVDIM * DMODEL / 4);
    split_kernel<<<1024, 256>>>(w_o, woh, wol, DMODEL * DMODEL / 4);

    // Fused QKV projection (Q columns scaled by 1/sqrt(64) = 0.125)
    gemm_mma_kernel<<<dim3(QKV_N / BN, S / BM), 256, GEMM_SMEM>>>(
        xh, xl, wh, wl, nullptr, qkvh, qkvl, DMODEL, QKV_N, nullptr,
        DMODEL, 0.125f);

    // Tensor-core flash attention -> ctx hi/lo
    attn_tc_kernel<<<dim3(S / 128, NHEADS), 128, ATTN_SMEM>>>(qkvh, qkvl, ch, cl);

    // Output projection + bias (fp32 out)
    gemm_mma_kernel<<<dim3(DMODEL / BN, S / BM), 256, GEMM_SMEM>>>(
        ch, cl, woh, wol, out, nullptr, nullptr, DMODEL, DMODEL, b_o, 0, 1.0f);
}

// round 7
// speedup vs baseline: 1.1826x; 1.1826x over previous
#include <cuda_runtime.h>
#include <cuda_bf16.h>
#include <math.h>
#include <cstdint>

// Problem constants
#define S        2048
#define DMODEL   2048
#define NHEADS   32
#define NKVHEADS 8
#define HDIM     64
#define KVDIM    (NKVHEADS * HDIM)   // 512
#define QKV_N    3072                // fused Q(2048) + K(512) + V(512)

// ---------------------------------------------------------------------------
// Device-global scratch (allocation-free, graph-capturable)
// ---------------------------------------------------------------------------
__device__ __nv_bfloat16 g_xh[S * DMODEL],      g_xl[S * DMODEL];
__device__ __nv_bfloat16 g_wh[QKV_N * DMODEL],  g_wl[QKV_N * DMODEL];   // stacked Wq|Wk|Wv
__device__ __nv_bfloat16 g_woh[DMODEL * DMODEL], g_wol[DMODEL * DMODEL];
__device__ __nv_bfloat16 g_qkvh[S * QKV_N],     g_qkvl[S * QKV_N];
__device__ __nv_bfloat16 g_ch[S * DMODEL],      g_cl[S * DMODEL];

__device__ __forceinline__ uint32_t smem_u32(const void* p) {
    uint32_t a;
    asm("{ .reg .u64 t; cvta.to.shared.u64 t, %1; cvt.u32.u64 %0, t; }"
        : "=r"(a) : "l"(p));
    return a;
}

__device__ __forceinline__ uint32_t pack_bf2(float x, float y) {
    __nv_bfloat162 h = __floats2bfloat162_rn(x, y);
    return *(uint32_t*)&h;
}

#define MMA_BF16(d, a0, a1, a2, a3, b0, b1) \
    asm volatile( \
        "mma.sync.aligned.m16n8k16.row.col.f32.bf16.bf16.f32 " \
        "{%0,%1,%2,%3}, {%4,%5,%6,%7}, {%8,%9}, {%0,%1,%2,%3};" \
        : "+f"((d)[0]), "+f"((d)[1]), "+f"((d)[2]), "+f"((d)[3]) \
        : "r"(a0), "r"(a1), "r"(a2), "r"(a3), "r"(b0), "r"(b1))

#define CP_ASYNC16(dst, src) \
    asm volatile("cp.async.cg.shared.global [%0], [%1], 16;" :: "r"(dst), "l"(src))

#define LDSM_X4(r0, r1, r2, r3, addr) \
    asm volatile("ldmatrix.sync.aligned.m8n8.x4.shared.b16 {%0,%1,%2,%3}, [%4];" \
                 : "=r"(r0), "=r"(r1), "=r"(r2), "=r"(r3) : "r"(addr))

// ---------------------------------------------------------------------------
// fp32 -> (hi, lo) bf16 split kernel
// ---------------------------------------------------------------------------
__global__ __launch_bounds__(256) void split_kernel(
    const float* __restrict__ in, __nv_bfloat16* __restrict__ hi,
    __nv_bfloat16* __restrict__ lo, int n4)
{
    int i = blockIdx.x * blockDim.x + threadIdx.x;
    int stride = gridDim.x * blockDim.x;
    const float4* in4 = (const float4*)in;
    __nv_bfloat162* h2 = (__nv_bfloat162*)hi;
    __nv_bfloat162* l2 = (__nv_bfloat162*)lo;
    for (; i < n4; i += stride) {
        float4 v = in4[i];
        __nv_bfloat16 hx = __float2bfloat16_rn(v.x);
        __nv_bfloat16 hy = __float2bfloat16_rn(v.y);
        __nv_bfloat16 hz = __float2bfloat16_rn(v.z);
        __nv_bfloat16 hw = __float2bfloat16_rn(v.w);
        __nv_bfloat16 lx = __float2bfloat16_rn(v.x - __bfloat162float(hx));
        __nv_bfloat16 ly = __float2bfloat16_rn(v.y - __bfloat162float(hy));
        __nv_bfloat16 lz = __float2bfloat16_rn(v.z - __bfloat162float(hz));
        __nv_bfloat16 lw = __float2bfloat16_rn(v.w - __bfloat162float(hw));
        h2[2 * i + 0] = __nv_bfloat162(hx, hy);
        h2[2 * i + 1] = __nv_bfloat162(hz, hw);
        l2[2 * i + 0] = __nv_bfloat162(lx, ly);
        l2[2 * i + 1] = __nv_bfloat162(lz, lw);
    }
}

// ---------------------------------------------------------------------------
// bf16 mma.sync GEMM, FUSED 3-term split per K-chunk:
//   per BK=32 chunk, load Ah,Al,Bh,Bl tiles once; issue Ah*Bh + Al*Bh + Ah*Bl.
// CTA 128x128, 256 threads (4M x 2N warps), warp tile 32x64.
// 2-stage cp.async pipeline, 2 CTAs/SM, row stride 80B (conflict-free ldmatrix).
// ---------------------------------------------------------------------------
#define BM 128
#define BN 128
#define BK2 32
#define RSTR 80                          // smem row stride bytes (64 + 16 pad)
#define TIL32 (128 * RSTR)               // 10240 per tile
#define STAGE4 (4 * TIL32)               // 40960 per stage (Ah,Al,Bh,Bl)
#define GEMM_SMEM (2 * STAGE4)           // 81920

__global__ __launch_bounds__(256, 2) void gemm_mma_kernel(
    const __nv_bfloat16* __restrict__ Ah, const __nv_bfloat16* __restrict__ Al,
    const __nv_bfloat16* __restrict__ Bh, const __nv_bfloat16* __restrict__ Bl,
    float* __restrict__ Cf, __nv_bfloat16* __restrict__ Chi,
    __nv_bfloat16* __restrict__ Clo,
    int Ktot, int Ncols, const float* __restrict__ bias,
    int qcols, float qscale)
{
    extern __shared__ __align__(16) char smem[];
    const uint32_t sbase = smem_u32(smem);

    const int tid   = threadIdx.x;
    const int lane  = tid & 31;
    const int wid   = tid >> 5;
    const int warpM = wid >> 1;      // 0..3
    const int warpN = wid & 1;       // 0..1
    const int g     = lane >> 2;
    const int t     = lane & 3;
    const int mb = blockIdx.y, nb = blockIdx.x;

    const int KT = Ktot / BK2;       // number of K chunks
    const size_t rowKb = (size_t)Ktot * 2;
    const size_t aOff = (size_t)(mb * BM) * rowKb;
    const size_t bOff = (size_t)(nb * BN) * rowKb;

    float acc[2][8][4];
#pragma unroll
    for (int mt = 0; mt < 2; ++mt)
#pragma unroll
        for (int nt = 0; nt < 8; ++nt)
#pragma unroll
            for (int c = 0; c < 4; ++c) acc[mt][nt][c] = 0.f;

    auto load_stage = [&](int kt, int stg) {
        const size_t kkb = (size_t)kt * (BK2 * 2);
        const char* s0 = (const char*)Ah + aOff + kkb;
        const char* s1 = (const char*)Al + aOff + kkb;
        const char* s2 = (const char*)Bh + bOff + kkb;
        const char* s3 = (const char*)Bl + bOff + kkb;
        const uint32_t sbeg = sbase + stg * STAGE4;
        // each tile: 128 rows x 4 granules of 16B; 512 granules, 256 threads -> 2 each
#pragma unroll
        for (int c = tid; c < 512; c += 256) {
            const int row = c >> 2, ch = c & 3;
            const uint32_t so = row * RSTR + ch * 16;
            const size_t go = (size_t)row * rowKb + ch * 16;
            CP_ASYNC16(sbeg + so,              s0 + go);
            CP_ASYNC16(sbeg + TIL32 + so,      s1 + go);
            CP_ASYNC16(sbeg + 2 * TIL32 + so,  s2 + go);
            CP_ASYNC16(sbeg + 3 * TIL32 + so,  s3 + go);
        }
        asm volatile("cp.async.commit_group;");
    };

    // ldmatrix per-lane address components (byte offsets within a tile)
    const uint32_t aRowOff = (uint32_t)((warpM * 32 + (lane & 15)) * RSTR
                                        + ((lane >> 4) << 4));
    const uint32_t bRowOff = (uint32_t)((warpN * 64 + ((lane >> 4) & 1) * 8 + (lane & 7)) * RSTR
                                        + (((lane >> 3) & 1) << 4));

    auto compute = [&](int stg) {
        const uint32_t aHT = sbase + stg * STAGE4;
        const uint32_t aLT = aHT + TIL32;
        const uint32_t bHT = aHT + 2 * TIL32;
        const uint32_t bLT = aHT + 3 * TIL32;
#pragma unroll
        for (int ks = 0; ks < 2; ++ks) {
            uint32_t aH[2][4], aL[2][4];
#pragma unroll
            for (int mt = 0; mt < 2; ++mt) {
                LDSM_X4(aH[mt][0], aH[mt][1], aH[mt][2], aH[mt][3],
                        aHT + aRowOff + mt * (16 * RSTR) + ks * 32);
                LDSM_X4(aL[mt][0], aL[mt][1], aL[mt][2], aL[mt][3],
                        aLT + aRowOff + mt * (16 * RSTR) + ks * 32);
            }
#pragma unroll
            for (int j = 0; j < 4; ++j) {
                uint32_t h0, h1, h2, h3, l0, l1, l2, l3;
                LDSM_X4(h0, h1, h2, h3, bHT + bRowOff + j * (16 * RSTR) + ks * 32);
                LDSM_X4(l0, l1, l2, l3, bLT + bRowOff + j * (16 * RSTR) + ks * 32);
#pragma unroll
                for (int mt = 0; mt < 2; ++mt) {
                    MMA_BF16(acc[mt][2 * j],     aH[mt][0], aH[mt][1], aH[mt][2], aH[mt][3], h0, h1);
                    MMA_BF16(acc[mt][2 * j],     aL[mt][0], aL[mt][1], aL[mt][2], aL[mt][3], h0, h1);
                    MMA_BF16(acc[mt][2 * j],     aH[mt][0], aH[mt][1], aH[mt][2], aH[mt][3], l0, l1);
                    MMA_BF16(acc[mt][2 * j + 1], aH[mt][0], aH[mt][1], aH[mt][2], aH[mt][3], h2, h3);
                    MMA_BF16(acc[mt][2 * j + 1], aL[mt][0], aL[mt][1], aL[mt][2], aL[mt][3], h2, h3);
                    MMA_BF16(acc[mt][2 * j + 1], aH[mt][0], aH[mt][1], aH[mt][2], aH[mt][3], l2, l3);
                }
            }
        }
    };

    // 2-stage pipeline: prologue
    load_stage(0, 0);

    for (int kt = 0; kt < KT; ++kt) {
        asm volatile("cp.async.wait_group 0;");
        __syncthreads();
        if (kt + 1 < KT) load_stage(kt + 1, (kt + 1) & 1);
        compute(kt & 1);
    }

    // Epilogue
    const int colBase = nb * BN;
    const float sc = (colBase < qcols) ? qscale : 1.0f;
    const int row0 = mb * BM + warpM * 32 + g;
    const int col0 = colBase + warpN * 64 + t * 2;
#pragma unroll
    for (int mt = 0; mt < 2; ++mt) {
#pragma unroll
        for (int nt = 0; nt < 8; ++nt) {
            const int col = col0 + nt * 8;
            const int rA = row0 + mt * 16;
            const int rB = rA + 8;
            float f0 = acc[mt][nt][0] * sc, f1 = acc[mt][nt][1] * sc;
            float f2 = acc[mt][nt][2] * sc, f3 = acc[mt][nt][3] * sc;
            if (Cf) {
                float bx = 0.f, by = 0.f;
                if (bias) { bx = bias[col]; by = bias[col + 1]; }
                *(float2*)(Cf + (size_t)rA * Ncols + col) = make_float2(f0 + bx, f1 + by);
                *(float2*)(Cf + (size_t)rB * Ncols + col) = make_float2(f2 + bx, f3 + by);
            } else {
                __nv_bfloat162 hA = __floats2bfloat162_rn(f0, f1);
                __nv_bfloat162 hB = __floats2bfloat162_rn(f2, f3);
                __nv_bfloat162 lA = __floats2bfloat162_rn(
                    f0 - __bfloat162float(hA.x), f1 - __bfloat162float(hA.y));
                __nv_bfloat162 lB = __floats2bfloat162_rn(
                    f2 - __bfloat162float(hB.x), f3 - __bfloat162float(hB.y));
                *(__nv_bfloat162*)(Chi + (size_t)rA * Ncols + col) = hA;
                *(__nv_bfloat162*)(Chi + (size_t)rB * Ncols + col) = hB;
                *(__nv_bfloat162*)(Clo + (size_t)rA * Ncols + col) = lA;
                *(__nv_bfloat162*)(Clo + (size_t)rB * Ncols + col) = lB;
            }
        }
    }
}

// ---------------------------------------------------------------------------
// Tensor-core causal flash attention (fused QKV input, stride 3072).
// BQ=128 per CTA, BKV=64 per iter, 4 warps. ldmatrix for all fragments.
// ---------------------------------------------------------------------------
#define ATS 72
#define AT_QBYTES (128 * ATS * 2)
#define AT_TBYTES (64 * ATS * 2)
#define ATTN_SMEM (2 * AT_QBYTES + 8 * AT_TBYTES)   // 110592

__global__ __launch_bounds__(128) void attn_tc_kernel(
    const __nv_bfloat16* __restrict__ QKVh, const __nv_bfloat16* __restrict__ QKVl,
    __nv_bfloat16* __restrict__ Ch, __nv_bfloat16* __restrict__ Cl)
{
    extern __shared__ __align__(16) char smem[];
    const int qb  = (int)gridDim.x - 1 - (int)blockIdx.x;
    const int h   = blockIdx.y;
    const int kvh = h >> 2;
    const int tid = threadIdx.x, wid = tid >> 5, lane = tid & 31;
    const int g = lane >> 2, t = lane & 3;

    const uint32_t uQh = smem_u32(smem);
    const uint32_t uQl = uQh + AT_QBYTES;
    const uint32_t uKV = uQl + AT_QBYTES;

    const size_t rowB = QKV_N * 2;

    // Q loads (once)
    {
        const char* srcH = (const char*)(QKVh + (size_t)(qb * 128) * QKV_N + h * HDIM);
        const char* srcL = (const char*)(QKVl + (size_t)(qb * 128) * QKV_N + h * HDIM);
#pragma unroll
        for (int c = tid; c < 1024; c += 128) {
            const int row = c >> 3, ch = c & 7;
            const uint32_t so = row * 144 + ch * 16;
            const size_t go = (size_t)row * rowB + ch * 16;
            CP_ASYNC16(uQh + so, srcH + go);
            CP_ASYNC16(uQl + so, srcL + go);
        }
    }

    const size_t koff = (size_t)DMODEL + kvh * HDIM;
    const size_t voff = (size_t)DMODEL + KVDIM + kvh * HDIM;

    auto load_kv = [&](int jb, int buf) {
        const size_t gbase = (size_t)(jb * 64) * QKV_N;
        const __nv_bfloat16* srcs[4] = {QKVh + gbase + koff, QKVl + gbase + koff,
                                        QKVh + gbase + voff, QKVl + gbase + voff};
#pragma unroll
        for (int w4 = 0; w4 < 4; ++w4) {
            const char* src = (const char*)srcs[w4];
            const uint32_t dst = uKV + (buf * 4 + w4) * AT_TBYTES;
#pragma unroll
            for (int c = tid; c < 512; c += 128) {
                const int row = c >> 3, ch = c & 7;
                CP_ASYNC16(dst + row * 144 + ch * 16,
                           src + (size_t)row * rowB + ch * 16);
            }
        }
    };

    load_kv(0, 0);
    asm volatile("cp.async.commit_group;");

    float o[2][8][4];
#pragma unroll
    for (int mt = 0; mt < 2; ++mt)
#pragma unroll
        for (int nt = 0; nt < 8; ++nt)
#pragma unroll
            for (int c = 0; c < 4; ++c) o[mt][nt][c] = 0.f;
    float mst[2][2] = {{-1e30f, -1e30f}, {-1e30f, -1e30f}};
    float lst[2][2] = {{0.f, 0.f}, {0.f, 0.f}};

    const int jbmax = 2 * qb + 1;

    const uint32_t qRowOff = (uint32_t)((wid * 32 + (lane & 15)) * 144
                                        + ((lane >> 4) << 4));
    const uint32_t kRowOff = (uint32_t)((((lane >> 4) & 1) * 8 + (lane & 7)) * 144
                                        + (((lane >> 3) & 1) << 4));

    for (int jb = 0; jb <= jbmax; ++jb) {
        const int buf = jb & 1;
        asm volatile("cp.async.wait_group 0;");
        __syncthreads();
        if (jb + 1 <= jbmax) {
            load_kv(jb + 1, buf ^ 1);
            asm volatile("cp.async.commit_group;");
        }

        float s[2][8][4];
#pragma unroll
        for (int mt = 0; mt < 2; ++mt)
#pragma unroll
            for (int nt = 0; nt < 8; ++nt)
#pragma unroll
                for (int c = 0; c < 4; ++c) s[mt][nt][c] = 0.f;

        const uint32_t uKhT = uKV + (buf * 4 + 0) * AT_TBYTES;
        const uint32_t uKlT = uKV + (buf * 4 + 1) * AT_TBYTES;
        const uint32_t uVhT = uKV + (buf * 4 + 2) * AT_TBYTES;
        const uint32_t uVlT = uKV + (buf * 4 + 3) * AT_TBYTES;

#pragma unroll
        for (int ks = 0; ks < 4; ++ks) {
            uint32_t aH[2][4], aL[2][4];
#pragma unroll
            for (int mt = 0; mt < 2; ++mt) {
                LDSM_X4(aH[mt][0], aH[mt][1], aH[mt][2], aH[mt][3],
                        uQh + qRowOff + mt * (16 * 144) + ks * 32);
                LDSM_X4(aL[mt][0], aL[mt][1], aL[mt][2], aL[mt][3],
                        uQl + qRowOff + mt * (16 * 144) + ks * 32);
            }
            uint32_t bh[8][2], bl[8][2];
#pragma unroll
            for (int j = 0; j < 4; ++j) {
                uint32_t r0, r1, r2, r3;
                LDSM_X4(r0, r1, r2, r3, uKhT + kRowOff + j * (16 * 144) + ks * 32);
                bh[2 * j][0] = r0; bh[2 * j][1] = r1;
                bh[2 * j + 1][0] = r2; bh[2 * j + 1][1] = r3;
                LDSM_X4(r0, r1, r2, r3, uKlT + kRowOff + j * (16 * 144) + ks * 32);
                bl[2 * j][0] = r0; bl[2 * j][1] = r1;
                bl[2 * j + 1][0] = r2; bl[2 * j + 1][1] = r3;
            }
#pragma unroll
            for (int nt = 0; nt < 8; ++nt)
#pragma unroll
                for (int mt = 0; mt < 2; ++mt) {
                    MMA_BF16(s[mt][nt], aH[mt][0], aH[mt][1], aH[mt][2], aH[mt][3],
                             bh[nt][0], bh[nt][1]);
                    MMA_BF16(s[mt][nt], aL[mt][0], aL[mt][1], aL[mt][2], aL[mt][3],
                             bh[nt][0], bh[nt][1]);
                    MMA_BF16(s[mt][nt], aH[mt][0], aH[mt][1], aH[mt][2], aH[mt][3],
                             bl[nt][0], bl[nt][1]);
                }
        }

        if (jb >= 2 * qb) {
            const int q0 = qb * 128 + wid * 32;
            const int kvb = jb * 64;
#pragma unroll
            for (int mt = 0; mt < 2; ++mt)
#pragma unroll
                for (int nt = 0; nt < 8; ++nt) {
                    const int kv0 = kvb + nt * 8 + 2 * t;
                    const int r0 = q0 + mt * 16 + g;
                    if (kv0 > r0)         s[mt][nt][0] = -1e30f;
                    if (kv0 + 1 > r0)     s[mt][nt][1] = -1e30f;
                    if (kv0 > r0 + 8)     s[mt][nt][2] = -1e30f;
                    if (kv0 + 1 > r0 + 8) s[mt][nt][3] = -1e30f;
                }
        }

#pragma unroll
        for (int mt = 0; mt < 2; ++mt)
#pragma unroll
            for (int hh = 0; hh < 2; ++hh) {
                float vmax = -1e30f;
#pragma unroll
                for (int nt = 0; nt < 8; ++nt)
                    vmax = fmaxf(vmax, fmaxf(s[mt][nt][2 * hh], s[mt][nt][2 * hh + 1]));
                vmax = fmaxf(vmax, __shfl_xor_sync(0xffffffffu, vmax, 1));
                vmax = fmaxf(vmax, __shfl_xor_sync(0xffffffffu, vmax, 2));
                const float mo = mst[mt][hh];
                const float mn = fmaxf(mo, vmax);
                const float corr = __expf(mo - mn);
                float ls = 0.f;
#pragma unroll
                for (int nt = 0; nt < 8; ++nt) {
                    float p0 = __expf(s[mt][nt][2 * hh] - mn);
                    float p1 = __expf(s[mt][nt][2 * hh + 1] - mn);
                    s[mt][nt][2 * hh] = p0;
                    s[mt][nt][2 * hh + 1] = p1;
                    ls += p0 + p1;
                }
                ls += __shfl_xor_sync(0xffffffffu, ls, 1);
                ls += __shfl_xor_sync(0xffffffffu, ls, 2);
                lst[mt][hh] = lst[mt][hh] * corr + ls;
                mst[mt][hh] = mn;
#pragma unroll
                for (int nt = 0; nt < 8; ++nt) {
                    o[mt][nt][2 * hh] *= corr;
                    o[mt][nt][2 * hh + 1] *= corr;
                }
            }

        uint32_t pH[2][8][2], pL[2][8][2];
#pragma unroll
        for (int mt = 0; mt < 2; ++mt)
#pragma unroll
            for (int nt = 0; nt < 8; ++nt) {
                float p0 = s[mt][nt][0], p1 = s[mt][nt][1];
                float p2 = s[mt][nt][2], p3 = s[mt][nt][3];
                __nv_bfloat162 h01 = __floats2bfloat162_rn(p0, p1);
                __nv_bfloat162 h23 = __floats2bfloat162_rn(p2, p3);
                pH[mt][nt][0] = *(uint32_t*)&h01;
                pH[mt][nt][1] = *(uint32_t*)&h23;
                pL[mt][nt][0] = pack_bf2(p0 - __bfloat162float(h01.x),
                                         p1 - __bfloat162float(h01.y));
                pL[mt][nt][1] = pack_bf2(p2 - __bfloat162float(h23.x),
                                         p3 - __bfloat162float(h23.y));
            }

        const uint32_t lmrow = lane & 15;
        const uint32_t lmcol = (lane >> 4) * 16;
#pragma unroll
        for (int kb = 0; kb < 4; ++kb) {
#pragma unroll
            for (int np = 0; np < 4; ++np) {
                const uint32_t lmoff = (kb * 16 + lmrow) * 144 + np * 32 + lmcol;
                uint32_t vh0, vh1, vh2, vh3, vl0, vl1, vl2, vl3;
                asm volatile("ldmatrix.sync.aligned.m8n8.x4.trans.shared.b16 "
                             "{%0,%1,%2,%3}, [%4];"
                             : "=r"(vh0), "=r"(vh1), "=r"(vh2), "=r"(vh3)
                             : "r"(uVhT + lmoff));
                asm volatile("ldmatrix.sync.aligned.m8n8.x4.trans.shared.b16 "
                             "{%0,%1,%2,%3}, [%4];"
                             : "=r"(vl0), "=r"(vl1), "=r"(vl2), "=r"(vl3)
                             : "r"(uVlT + lmoff));
#pragma unroll
                for (int mt = 0; mt < 2; ++mt) {
                    const uint32_t a0 = pH[mt][2 * kb][0], a1 = pH[mt][2 * kb][1];
                    const uint32_t a2 = pH[mt][2 * kb + 1][0], a3 = pH[mt][2 * kb + 1][1];
                    const uint32_t c0 = pL[mt][2 * kb][0], c1 = pL[mt][2 * kb][1];
                    const uint32_t c2 = pL[mt][2 * kb + 1][0], c3 = pL[mt][2 * kb + 1][1];
                    MMA_BF16(o[mt][2 * np], a0, a1, a2, a3, vh0, vh1);
                    MMA_BF16(o[mt][2 * np], c0, c1, c2, c3, vh0, vh1);
                    MMA_BF16(o[mt][2 * np], a0, a1, a2, a3, vl0, vl1);
                    MMA_BF16(o[mt][2 * np + 1], a0, a1, a2, a3, vh2, vh3);
                    MMA_BF16(o[mt][2 * np + 1], c0, c1, c2, c3, vh2, vh3);
                    MMA_BF16(o[mt][2 * np + 1], a0, a1, a2, a3, vl2, vl3);
                }
            }
        }
        __syncthreads();
    }

#pragma unroll
    for (int mt = 0; mt < 2; ++mt)
#pragma unroll
        for (int hh = 0; hh < 2; ++hh) {
            const float inv = 1.f / lst[mt][hh];
            const int row = qb * 128 + wid * 32 + mt * 16 + hh * 8 + g;
            const size_t gbase = (size_t)row * DMODEL + h * HDIM;
#pragma unroll
            for (int nt = 0; nt < 8; ++nt) {
                const int col = nt * 8 + 2 * t;
                float v0 = o[mt][nt][2 * hh] * inv;
                float v1 = o[mt][nt][2 * hh + 1] * inv;
                __nv_bfloat162 hv = __floats2bfloat162_rn(v0, v1);
                __nv_bfloat162 lv = __floats2bfloat162_rn(
                    v0 - __bfloat162float(hv.x), v1 - __bfloat162float(hv.y));
                *(__nv_bfloat162*)(Ch + gbase + col) = hv;
                *(__nv_bfloat162*)(Cl + gbase + col) = lv;
            }
        }
}

// ---------------------------------------------------------------------------
// Launcher
// ---------------------------------------------------------------------------
extern "C" void kernel_launch(void* const* d_in, const int* in_sizes, int n_in,
                              void* d_out, int out_size)
{
    const float* x   = (const float*)d_in[0];
    // d_in[1] = mask (int32 causal tril) — causality hardcoded
    const float* w_q = (const float*)d_in[2];
    const float* w_k = (const float*)d_in[3];
    const float* w_v = (const float*)d_in[4];
    const float* w_o = (const float*)d_in[5];
    const float* b_o = (const float*)d_in[6];
    float* out = (float*)d_out;

    __nv_bfloat16 *xh, *xl, *wh, *wl, *woh, *wol, *qkvh, *qkvl, *ch, *cl;
    cudaGetSymbolAddress((void**)&xh,   g_xh);   cudaGetSymbolAddress((void**)&xl,   g_xl);
    cudaGetSymbolAddress((void**)&wh,   g_wh);   cudaGetSymbolAddress((void**)&wl,   g_wl);
    cudaGetSymbolAddress((void**)&woh,  g_woh);  cudaGetSymbolAddress((void**)&wol,  g_wol);
    cudaGetSymbolAddress((void**)&qkvh, g_qkvh); cudaGetSymbolAddress((void**)&qkvl, g_qkvl);
    cudaGetSymbolAddress((void**)&ch,   g_ch);   cudaGetSymbolAddress((void**)&cl,   g_cl);

    cudaFuncSetAttribute(attn_tc_kernel, cudaFuncAttributeMaxDynamicSharedMemorySize,
                         ATTN_SMEM);
    cudaFuncSetAttribute(gemm_mma_kernel, cudaFuncAttributeMaxDynamicSharedMemorySize,
                         GEMM_SMEM);

    // Split inputs to bf16 hi/lo (weights stacked Wq|Wk|Wv)
    split_kernel<<<1024, 256>>>(x,   xh, xl, S * DMODEL / 4);
    split_kernel<<<1024, 256>>>(w_q, wh,                    wl,                    DMODEL * DMODEL / 4);
    split_kernel<<<1024, 256>>>(w_k, wh + DMODEL * DMODEL,  wl + DMODEL * DMODEL,  KVDIM * DMODEL / 4);
    split_kernel<<<1024, 256>>>(w_v, wh + (DMODEL + KVDIM) * DMODEL,
                                      wl + (DMODEL + KVDIM) * DMODEL, KVDIM * DMODEL / 4);
    split_kernel<<<1024, 256>>>(w_o, woh, wol, DMODEL * DMODEL / 4);

    // Fused QKV projection (Q columns scaled by 1/sqrt(64) = 0.125)
    gemm_mma_kernel<<<dim3(QKV_N / BN, S / BM), 256, GEMM_SMEM>>>(
        xh, xl, wh, wl, nullptr, qkvh, qkvl, DMODEL, QKV_N, nullptr,
        DMODEL, 0.125f);

    // Tensor-core flash attention -> ctx hi/lo
    attn_tc_kernel<<<dim3(S / 128, NHEADS), 128, ATTN_SMEM>>>(qkvh, qkvl, ch, cl);

    // Output projection + bias (fp32 out)
    gemm_mma_kernel<<<dim3(DMODEL / BN, S / BM), 256, GEMM_SMEM>>>(
        ch, cl, woh, wol, out, nullptr, nullptr, DMODEL, DMODEL, b_o, 0, 1.0f);
}